// round 2
// baseline (speedup 1.0000x reference)
#include <cuda_runtime.h>

#define TT       64
#define NN       2048
#define RPB      16                 // rows of w owned per CTA
#define NCTA     (NN / RPB)         // 128 CTAs
#define NTHREADS 1024
#define NWARPS   (NTHREADS / 32)    // 32
#define CBLKS    16                 // 16 column blocks of 128 cols
#define CPB      128                // cols per block
#define RPW      8                  // rows per warp (2 row-groups x 16 col-blocks)

// shared-memory layout (floats)
#define SM_W     0
#define SM_TP    (RPB * NN)                 // 32768
#define SM_TPO   (SM_TP + NN)
#define SM_Z     (SM_TPO + NN)
#define SM_V     (SM_Z + NN)
#define SM_X     (SM_V + RPB)
#define SM_PART  (SM_X + RPB)               // part[cblk][row] = CBLKS*RPB
#define SM_TOTAL (SM_PART + CBLKS * RPB)
#define SMEM_BYTES (SM_TOTAL * sizeof(float))

// one-sided sync flags: flag[t][cta], monotonically incremented once per launch.
// Graph-replay safe: all flags equal at launch start; base is read from this
// CTA's own t=0 slot before anyone writes it.
__device__ unsigned g_flags[TT * NCTA];

__device__ __forceinline__ float clip01(float x) {
    return fminf(fmaxf(x, 0.0f), 1.0f);
}

__global__ void __launch_bounds__(NTHREADS, 1)
snn_persistent(const float* __restrict__ exc,
               const float* __restrict__ w_in,
               const float* __restrict__ tpre_in,
               const float* __restrict__ tpost_in,
               float* __restrict__ out)
{
    extern __shared__ float sm[];
    float* w_s   = sm + SM_W;     // RPB x NN row-major
    float* tp_s  = sm + SM_TP;    // NN
    float* tpo_s = sm + SM_TPO;   // NN
    float* z_s   = sm + SM_Z;     // NN
    float* v_s   = sm + SM_V;     // RPB
    float* x_s   = sm + SM_X;     // RPB
    float* part  = sm + SM_PART;  // [CBLKS][RPB]

    const int tid  = threadIdx.x;
    const int warp = tid >> 5;
    const int lane = tid & 31;
    const int bid  = blockIdx.x;
    const int rowBase = bid * RPB;

    const int cblk = warp & (CBLKS - 1);        // 0..15
    const int r0   = (warp >> 4) * RPW;         // 0 or 8
    const int colBase = cblk * CPB + lane * 4;

    // launch-uniform flag base (own t=0 slot, not yet written this launch)
    const unsigned target = g_flags[bid] + 1u;

    // ---- prologue: own 16 rows of w -> smem (only DRAM traffic) ----
    {
        const float4* src = reinterpret_cast<const float4*>(w_in + (size_t)rowBase * NN);
        float4*       dst = reinterpret_cast<float4*>(w_s);
        #pragma unroll
        for (int i = 0; i < RPB * NN / 4 / NTHREADS; ++i)
            dst[tid + i * NTHREADS] = src[tid + i * NTHREADS];
    }
    for (int i = tid; i < NN; i += NTHREADS) {
        tp_s[i]  = tpre_in[i];
        tpo_s[i] = tpost_in[i];
        z_s[i]   = 0.0f;
    }
    if (tid < RPB) v_s[tid] = 0.0f;
    __syncthreads();

    for (int t = 0; t < TT; ++t) {
        if (tid < RPB) x_s[tid] = exc[t * NN + rowBase + tid];

        // ---- fused pass: apply dw_{t-1}, compute i_syn = w_new @ z_{t-1} ----
        if (t > 0) {
            const float4 zv = *reinterpret_cast<const float4*>(&z_s[colBase]);
            const float4 pv = *reinterpret_cast<const float4*>(&tp_s[colBase]);
            float acc[RPW];
            #pragma unroll
            for (int r = 0; r < RPW; ++r) {
                const int R = r0 + r;
                const float a = __fmul_rn(1e-3f, z_s[rowBase + R]);
                const float b = __fmul_rn(1e-3f, tpo_s[rowBase + R]);
                float4 wv = *reinterpret_cast<float4*>(&w_s[R * NN + colBase]);

                wv.x = clip01(__fadd_rn(wv.x, __fsub_rn(__fmul_rn(a, pv.x), __fmul_rn(b, zv.x))));
                wv.y = clip01(__fadd_rn(wv.y, __fsub_rn(__fmul_rn(a, pv.y), __fmul_rn(b, zv.y))));
                wv.z = clip01(__fadd_rn(wv.z, __fsub_rn(__fmul_rn(a, pv.z), __fmul_rn(b, zv.z))));
                wv.w = clip01(__fadd_rn(wv.w, __fsub_rn(__fmul_rn(a, pv.w), __fmul_rn(b, zv.w))));

                *reinterpret_cast<float4*>(&w_s[R * NN + colBase]) = wv;

                float acc_r = wv.x * zv.x;
                acc_r = fmaf(wv.y, zv.y, acc_r);
                acc_r = fmaf(wv.z, zv.z, acc_r);
                acc_r = fmaf(wv.w, zv.w, acc_r);
                acc[r] = acc_r;
            }
            // batched, independent butterfly reductions (pipelined)
            #pragma unroll
            for (int r = 0; r < RPW; ++r) {
                #pragma unroll
                for (int off = 16; off; off >>= 1)
                    acc[r] += __shfl_xor_sync(0xffffffffu, acc[r], off);
            }
            if (lane == 0) {
                #pragma unroll
                for (int r = 0; r < RPW; ++r)
                    part[cblk * RPB + (r0 + r)] = acc[r];
            }
        }
        __syncthreads();

        // ---- neuron update for own 16 rows ----
        if (tid < RPB) {
            float isyn = 0.0f;
            if (t > 0) {
                #pragma unroll
                for (int k = 0; k < CBLKS; ++k) isyn += part[k * RPB + tid];
            }
            float v = v_s[tid];
            v = __fadd_rn(v, __fmul_rn(0.1f,
                    __fadd_rn(__fadd_rn(__fsub_rn(0.0f, v), isyn), x_s[tid])));
            const float zn = (__fsub_rn(v, 1.0f) > 0.0f) ? 1.0f : 0.0f;
            v_s[tid] = (zn > 0.0f) ? 0.0f : v;
            out[t * NN + rowBase + tid] = zn;
        }

        if (t == TT - 1) break;   // last step: no consumer of z_63

        // ---- one-sided release: publish flag after own spikes are visible ----
        __syncthreads();
        if (tid == 0) {
            __threadfence();
            *((volatile unsigned*)&g_flags[t * NCTA + bid]) = target;
        }
        // ---- acquire: wait for all 128 CTAs' step-t flags ----
        if (tid < NCTA) {
            while (*((volatile unsigned*)&g_flags[t * NCTA + tid]) != target) { }
            __threadfence();
        }
        __syncthreads();

        // ---- read full z_t (L2, bypass L1); update traces locally ----
        {
            const float2 zr = __ldcg(reinterpret_cast<const float2*>(out + (size_t)t * NN) + tid);
            const int i0 = tid * 2;
            *reinterpret_cast<float2*>(&z_s[i0]) = zr;

            float2 p = *reinterpret_cast<float2*>(&tp_s[i0]);
            float2 q = *reinterpret_cast<float2*>(&tpo_s[i0]);
            p.x = __fadd_rn(p.x, __fmul_rn(0.05f, __fadd_rn(-p.x, zr.x)));
            p.y = __fadd_rn(p.y, __fmul_rn(0.05f, __fadd_rn(-p.y, zr.y)));
            q.x = __fadd_rn(q.x, __fmul_rn(0.05f, __fadd_rn(-q.x, zr.x)));
            q.y = __fadd_rn(q.y, __fmul_rn(0.05f, __fadd_rn(-q.y, zr.y)));
            *reinterpret_cast<float2*>(&tp_s[i0])  = p;
            *reinterpret_cast<float2*>(&tpo_s[i0]) = q;
        }
        __syncthreads();
    }
}

extern "C" void kernel_launch(void* const* d_in, const int* in_sizes, int n_in,
                              void* d_out, int out_size) {
    const float* exc   = (const float*)d_in[0];  // [T, N]
    const float* w     = (const float*)d_in[1];  // [N, N]
    const float* tpre  = (const float*)d_in[2];  // [N]
    const float* tpost = (const float*)d_in[3];  // [N]
    float*       out   = (float*)d_out;          // [T, N]

    cudaFuncSetAttribute(snn_persistent,
                         cudaFuncAttributeMaxDynamicSharedMemorySize,
                         (int)SMEM_BYTES);
    snn_persistent<<<NCTA, NTHREADS, SMEM_BYTES>>>(exc, w, tpre, tpost, out);
}

// round 3
// speedup vs baseline: 1.8205x; 1.8205x over previous
#include <cuda_runtime.h>

#define TT       64
#define NN       2048
#define RPB      16                 // rows of w owned per CTA
#define NCTA     (NN / RPB)         // 128 CTAs (1 per SM)
#define NTHREADS 512
#define NWARPS   (NTHREADS / 32)    // 16 warps = 16 column blocks
#define CPB      128                // cols per warp block

// shared-memory layout (floats)
#define SM_W     0
#define SM_TP    (RPB * NN)                 // 32768
#define SM_TPO   (SM_TP + NN)
#define SM_Z     (SM_TPO + NN)
#define SM_PART  (SM_Z + NN)                // part[warp][row] = 16*16
#define SM_TOTAL (SM_PART + NWARPS * RPB)
#define SMEM_BYTES (SM_TOTAL * sizeof(float))

// global barrier state: monotonic gen + arrival count (graph-replay safe:
// count returns to 0 every barrier, gen is compared by snapshot, never reset)
__device__ unsigned g_cnt = 0;
__device__ unsigned g_gen = 0;

__device__ __forceinline__ float clip01(float x) {
    return fminf(fmaxf(x, 0.0f), 1.0f);
}

__global__ void __launch_bounds__(NTHREADS, 1)
snn_persistent(const float* __restrict__ exc,
               const float* __restrict__ w_in,
               const float* __restrict__ tpre_in,
               const float* __restrict__ tpost_in,
               float* __restrict__ out)
{
    extern __shared__ float sm[];
    float* w_s   = sm + SM_W;     // RPB x NN row-major
    float* tp_s  = sm + SM_TP;    // NN
    float* tpo_s = sm + SM_TPO;   // NN
    float* z_s   = sm + SM_Z;     // NN
    float* part  = sm + SM_PART;  // [NWARPS][RPB]

    const int tid  = threadIdx.x;
    const int warp = tid >> 5;
    const int lane = tid & 31;
    const int bid  = blockIdx.x;
    const int rowBase = bid * RPB;
    const int colBase = warp * CPB + lane * 4;

    // ---- prologue: own 16 rows of w -> smem (only DRAM traffic) ----
    {
        const float4* src = reinterpret_cast<const float4*>(w_in + (size_t)rowBase * NN);
        float4*       dst = reinterpret_cast<float4*>(w_s);
        #pragma unroll
        for (int i = 0; i < RPB * NN / 4 / NTHREADS; ++i)
            dst[tid + i * NTHREADS] = src[tid + i * NTHREADS];
    }
    for (int i = tid; i < NN; i += NTHREADS) {
        tp_s[i]  = tpre_in[i];
        tpo_s[i] = tpost_in[i];
        z_s[i]   = 0.0f;
    }
    float v = 0.0f;                // membrane potential (warp0, lane<16 only)
    __syncthreads();

    for (int t = 0; t < TT; ++t) {
        // early loads: own input current (register, warp0), barrier snapshot (warp1).
        // snap is read before syncthreads(1): barrier t cannot complete before our
        // warp0 arrives (which is after syncthreads(1)), so snap is exact.
        float x = 0.0f;
        if (warp == 0 && lane < RPB) x = __ldcg(&exc[t * NN + rowBase + lane]);
        unsigned snap = 0;
        if (warp == 1 && lane == 0) snap = *((volatile unsigned*)&g_gen);

        // ---- fused pass: apply dw_{t-1} to w, compute i_syn = w_new @ z_{t-1} ----
        if (t > 0) {
            const float4 zv = *reinterpret_cast<const float4*>(&z_s[colBase]);
            const float4 pv = *reinterpret_cast<const float4*>(&tp_s[colBase]);

            // preload per-row scalars (broadcast LDS, hoisted out of hot loop)
            float a[RPB], b[RPB];
            #pragma unroll
            for (int r = 0; r < RPB; ++r) {
                a[r] = __fmul_rn(1e-3f, z_s[rowBase + r]);
                b[r] = __fmul_rn(1e-3f, tpo_s[rowBase + r]);
            }

            float acc[RPB];
            #pragma unroll
            for (int half = 0; half < 2; ++half) {
                // batch-load 8 rows (8 LDS.128 in flight -> latency covered)
                float4 wv[8];
                #pragma unroll
                for (int r = 0; r < 8; ++r)
                    wv[r] = *reinterpret_cast<float4*>(&w_s[(half * 8 + r) * NN + colBase]);
                #pragma unroll
                for (int r = 0; r < 8; ++r) {
                    const int R = half * 8 + r;
                    float4 w4 = wv[r];
                    // dw = 1e-3*z[i]*tp[j] - 1e-3*tpo[i]*z[j]  (exact, no fma fusion)
                    w4.x = clip01(__fadd_rn(w4.x, __fsub_rn(__fmul_rn(a[R], pv.x), __fmul_rn(b[R], zv.x))));
                    w4.y = clip01(__fadd_rn(w4.y, __fsub_rn(__fmul_rn(a[R], pv.y), __fmul_rn(b[R], zv.y))));
                    w4.z = clip01(__fadd_rn(w4.z, __fsub_rn(__fmul_rn(a[R], pv.z), __fmul_rn(b[R], zv.z))));
                    w4.w = clip01(__fadd_rn(w4.w, __fsub_rn(__fmul_rn(a[R], pv.w), __fmul_rn(b[R], zv.w))));
                    *reinterpret_cast<float4*>(&w_s[R * NN + colBase]) = w4;

                    float d = w4.x * zv.x;
                    d = fmaf(w4.y, zv.y, d);
                    d = fmaf(w4.z, zv.z, d);
                    d = fmaf(w4.w, zv.w, d);
                    acc[R] = d;
                }
            }

            // multi-value tree reduction: 16 accs x 32 lanes -> 16 row sums.
            // level off: lanes with (lane&off) own the upper half of rows.
            #pragma unroll
            for (int r = 0; r < 8; ++r) {
                float keep = (lane & 16) ? acc[r + 8] : acc[r];
                float send = (lane & 16) ? acc[r]     : acc[r + 8];
                acc[r] = keep + __shfl_xor_sync(0xffffffffu, send, 16);
            }
            #pragma unroll
            for (int r = 0; r < 4; ++r) {
                float keep = (lane & 8) ? acc[r + 4] : acc[r];
                float send = (lane & 8) ? acc[r]     : acc[r + 4];
                acc[r] = keep + __shfl_xor_sync(0xffffffffu, send, 8);
            }
            #pragma unroll
            for (int r = 0; r < 2; ++r) {
                float keep = (lane & 4) ? acc[r + 2] : acc[r];
                float send = (lane & 4) ? acc[r]     : acc[r + 2];
                acc[r] = keep + __shfl_xor_sync(0xffffffffu, send, 4);
            }
            {
                float keep = (lane & 2) ? acc[1] : acc[0];
                float send = (lane & 2) ? acc[0] : acc[1];
                acc[0] = keep + __shfl_xor_sync(0xffffffffu, send, 2);
            }
            acc[0] += __shfl_xor_sync(0xffffffffu, acc[0], 1);
            // lane l holds the sum for row (l>>1); even lanes publish
            if ((lane & 1) == 0) part[warp * RPB + (lane >> 1)] = acc[0];
        }
        __syncthreads();   // (1) part[] complete

        // ---- neuron update + release (warp 0 only) ----
        if (warp == 0) {
            if (lane < RPB) {
                float isyn = 0.0f;
                if (t > 0) {
                    #pragma unroll
                    for (int k = 0; k < NWARPS; ++k) isyn += part[k * RPB + lane];
                }
                v = __fadd_rn(v, __fmul_rn(0.1f, __fadd_rn(__fadd_rn(-v, isyn), x)));
                const float zn = (__fsub_rn(v, 1.0f) > 0.0f) ? 1.0f : 0.0f;
                v = (zn > 0.0f) ? 0.0f : v;
                out[t * NN + rowBase + lane] = zn;
            }
            if (t < TT - 1) {
                __syncwarp();
                __threadfence();
                if (lane == 0) {
                    unsigned old = atomicAdd(&g_cnt, 1u);
                    if (old == NCTA - 1u) {
                        *((volatile unsigned*)&g_cnt) = 0u;
                        __threadfence();
                        atomicAdd(&g_gen, 1u);   // release
                    }
                }
            }
        }
        if (t == TT - 1) break;   // z_63 has no consumer

        // ---- acquire: single poller per CTA ----
        if (warp == 1 && lane == 0) {
            while (*((volatile unsigned*)&g_gen) == snap) { }
            __threadfence();
        }
        __syncthreads();   // (2) all warps see remote spikes via warp1's acquire

        // ---- read full z_t; update traces (replicated locally) ----
        {
            const int i0 = tid * 4;
            const float4 zr = __ldcg(reinterpret_cast<const float4*>(out + (size_t)t * NN) + tid);
            *reinterpret_cast<float4*>(&z_s[i0]) = zr;

            float4 p = *reinterpret_cast<float4*>(&tp_s[i0]);
            float4 q = *reinterpret_cast<float4*>(&tpo_s[i0]);
            p.x = __fadd_rn(p.x, __fmul_rn(0.05f, __fadd_rn(-p.x, zr.x)));
            p.y = __fadd_rn(p.y, __fmul_rn(0.05f, __fadd_rn(-p.y, zr.y)));
            p.z = __fadd_rn(p.z, __fmul_rn(0.05f, __fadd_rn(-p.z, zr.z)));
            p.w = __fadd_rn(p.w, __fmul_rn(0.05f, __fadd_rn(-p.w, zr.w)));
            q.x = __fadd_rn(q.x, __fmul_rn(0.05f, __fadd_rn(-q.x, zr.x)));
            q.y = __fadd_rn(q.y, __fmul_rn(0.05f, __fadd_rn(-q.y, zr.y)));
            q.z = __fadd_rn(q.z, __fmul_rn(0.05f, __fadd_rn(-q.z, zr.z)));
            q.w = __fadd_rn(q.w, __fmul_rn(0.05f, __fadd_rn(-q.w, zr.w)));
            *reinterpret_cast<float4*>(&tp_s[i0])  = p;
            *reinterpret_cast<float4*>(&tpo_s[i0]) = q;
        }
        __syncthreads();   // (3) traces/z ready for next fused pass
    }
}

extern "C" void kernel_launch(void* const* d_in, const int* in_sizes, int n_in,
                              void* d_out, int out_size) {
    const float* exc   = (const float*)d_in[0];  // [T, N]
    const float* w     = (const float*)d_in[1];  // [N, N]
    const float* tpre  = (const float*)d_in[2];  // [N]
    const float* tpost = (const float*)d_in[3];  // [N]
    float*       out   = (float*)d_out;          // [T, N]

    cudaFuncSetAttribute(snn_persistent,
                         cudaFuncAttributeMaxDynamicSharedMemorySize,
                         (int)SMEM_BYTES);
    snn_persistent<<<NCTA, NTHREADS, SMEM_BYTES>>>(exc, w, tpre, tpost, out);
}